// round 1
// baseline (speedup 1.0000x reference)
#include <cuda_runtime.h>
#include <cstdint>

// Problem constants (fixed by the reference): B=2,H=8 -> BH=16, N=M=2048, D=128
#define BH_   16
#define NN_   2048
#define MM_   2048
#define DD    128

#define BN    128   // N rows per CTA
#define BM    32    // M chunk per mainloop iteration
#define NTHREADS 256

// SMEM strides (floats), padded for conflict-free fragment loads
#define QSTR  132   // Q/K/U tiles: bank stride 4 per row -> conflict-free A/B frag LDS
#define VSTR  136   // V tile: bank stride 8 per row -> conflict-free B frag LDS
#define HSTR  36    // Hid tile

__device__ __forceinline__ float to_tf32(float x) {
    float y;
    asm("cvt.rna.tf32.f32 %0, %1;" : "=f"(y) : "f"(x));
    return y;
}

__device__ __forceinline__ void mma_tf32(float c[4],
                                         uint32_t a0, uint32_t a1, uint32_t a2, uint32_t a3,
                                         uint32_t b0, uint32_t b1) {
    asm volatile(
        "mma.sync.aligned.m16n8k8.row.col.f32.tf32.tf32.f32 "
        "{%0,%1,%2,%3}, {%4,%5,%6,%7}, {%8,%9}, {%0,%1,%2,%3};"
        : "+f"(c[0]), "+f"(c[1]), "+f"(c[2]), "+f"(c[3])
        : "r"(a0), "r"(a1), "r"(a2), "r"(a3), "r"(b0), "r"(b1));
}

__global__ __launch_bounds__(NTHREADS)
void ffnmoe_kernel(const float* __restrict__ Q, const float* __restrict__ K,
                   const float* __restrict__ U, const float* __restrict__ V,
                   const float* __restrict__ R, float* __restrict__ O) {
    extern __shared__ float sm[];
    float* sQ = sm;                    // BN * QSTR
    float* sK = sQ + BN * QSTR;        // BM * QSTR
    float* sU = sK + BM * QSTR;        // BM * QSTR
    float* sV = sU + BM * QSTR;        // BM * VSTR
    float* sH = sV + BM * VSTR;        // BN * HSTR

    const int bh  = blockIdx.y;
    const int n0  = blockIdx.x * BN;
    const int tid = threadIdx.x;
    const int lane = tid & 31;
    const int warp = tid >> 5;
    const int g  = lane >> 2;          // 0..7
    const int t4 = lane & 3;           // 0..3
    const int warpN = warp >> 1;       // 0..3 (row group of 32)
    const int warpM = warp & 1;        // 0..1

    const float* gQ = Q + ((size_t)bh * NN_ + n0) * DD;
    const float* gK = K + (size_t)bh * MM_ * DD;
    const float* gU = U + (size_t)bh * MM_ * DD;
    const float* gV = V + (size_t)bh * MM_ * DD;
    const float* gR = R + ((size_t)bh * NN_ + n0) * (size_t)MM_;
    float*       gO = O + ((size_t)bh * NN_ + n0) * DD;

    // ---- Load Q tile (128x128) into SMEM as tf32 ----
    for (int f = tid; f < BN * DD / 4; f += NTHREADS) {
        int row = f >> 5;
        int c4  = (f & 31) << 2;
        float4 v = *(const float4*)(gQ + (size_t)row * DD + c4);
        v.x = to_tf32(v.x); v.y = to_tf32(v.y); v.z = to_tf32(v.z); v.w = to_tf32(v.w);
        *(float4*)(sQ + row * QSTR + c4) = v;
    }

    // O accumulators: warp tile 32(rows) x 64(cols) = 2 mtiles x 8 ntiles
    float accO[2][8][4];
    #pragma unroll
    for (int i = 0; i < 2; i++)
        #pragma unroll
        for (int j = 0; j < 8; j++)
            #pragma unroll
            for (int k = 0; k < 4; k++) accO[i][j][k] = 0.f;

    for (int m0 = 0; m0 < MM_; m0 += BM) {
        __syncthreads();   // previous iteration done reading sK/sU/sV/sH

        // ---- Load K, U, V chunks (32x128 each) as tf32 ----
        for (int f = tid; f < BM * DD / 4; f += NTHREADS) {
            int row = f >> 5;
            int c4  = (f & 31) << 2;
            size_t goff = (size_t)(m0 + row) * DD + c4;
            float4 kv = *(const float4*)(gK + goff);
            float4 uv = *(const float4*)(gU + goff);
            float4 vv = *(const float4*)(gV + goff);
            float4 a;
            a.x = to_tf32(kv.x); a.y = to_tf32(kv.y); a.z = to_tf32(kv.z); a.w = to_tf32(kv.w);
            *(float4*)(sK + row * QSTR + c4) = a;
            a.x = to_tf32(uv.x); a.y = to_tf32(uv.y); a.z = to_tf32(uv.z); a.w = to_tf32(uv.w);
            *(float4*)(sU + row * QSTR + c4) = a;
            a.x = to_tf32(vv.x); a.y = to_tf32(vv.y); a.z = to_tf32(vv.z); a.w = to_tf32(vv.w);
            *(float4*)(sV + row * VSTR + c4) = a;
        }
        __syncthreads();

        // ---- GEMM1: S = Q*K^T, T = Q*U^T   (warp tile 32x16 of a 128x32 S/T) ----
        float accS[2][2][4] = {};
        float accT[2][2][4] = {};
        #pragma unroll
        for (int kk = 0; kk < DD / 8; kk++) {
            const int k8 = kk * 8;
            uint32_t a[2][4];
            #pragma unroll
            for (int mt = 0; mt < 2; mt++) {
                int rA = warpN * 32 + mt * 16 + g;
                a[mt][0] = __float_as_uint(sQ[rA * QSTR + k8 + t4]);
                a[mt][1] = __float_as_uint(sQ[(rA + 8) * QSTR + k8 + t4]);
                a[mt][2] = __float_as_uint(sQ[rA * QSTR + k8 + t4 + 4]);
                a[mt][3] = __float_as_uint(sQ[(rA + 8) * QSTR + k8 + t4 + 4]);
            }
            #pragma unroll
            for (int nt = 0; nt < 2; nt++) {
                int cB = (warpM * 16 + nt * 8 + g) * QSTR + k8 + t4;
                uint32_t bk0 = __float_as_uint(sK[cB]);
                uint32_t bk1 = __float_as_uint(sK[cB + 4]);
                uint32_t bu0 = __float_as_uint(sU[cB]);
                uint32_t bu1 = __float_as_uint(sU[cB + 4]);
                #pragma unroll
                for (int mt = 0; mt < 2; mt++) {
                    mma_tf32(accS[mt][nt], a[mt][0], a[mt][1], a[mt][2], a[mt][3], bk0, bk1);
                    mma_tf32(accT[mt][nt], a[mt][0], a[mt][1], a[mt][2], a[mt][3], bu0, bu1);
                }
            }
        }

        // ---- Elementwise: Hid = relu(S) * T * R  -> sH (tf32) ----
        #pragma unroll
        for (int mt = 0; mt < 2; mt++) {
            #pragma unroll
            for (int nt = 0; nt < 2; nt++) {
                int row  = warpN * 32 + mt * 16 + g;
                int colL = warpM * 16 + nt * 8 + 2 * t4;
                const float2 r0 = *(const float2*)(gR + (size_t)row * MM_ + m0 + colL);
                const float2 r1 = *(const float2*)(gR + (size_t)(row + 8) * MM_ + m0 + colL);
                float h0 = fmaxf(accS[mt][nt][0], 0.f) * accT[mt][nt][0] * r0.x;
                float h1 = fmaxf(accS[mt][nt][1], 0.f) * accT[mt][nt][1] * r0.y;
                float h2 = fmaxf(accS[mt][nt][2], 0.f) * accT[mt][nt][2] * r1.x;
                float h3 = fmaxf(accS[mt][nt][3], 0.f) * accT[mt][nt][3] * r1.y;
                float2 w0; w0.x = to_tf32(h0); w0.y = to_tf32(h1);
                float2 w1; w1.x = to_tf32(h2); w1.y = to_tf32(h3);
                *(float2*)(sH + row * HSTR + colL) = w0;
                *(float2*)(sH + (row + 8) * HSTR + colL) = w1;
            }
        }
        __syncthreads();

        // ---- GEMM2: O += Hid * V   (warp tile 32 x 64 of the 128x128 O) ----
        #pragma unroll
        for (int kk = 0; kk < BM / 8; kk++) {
            const int k8 = kk * 8;
            uint32_t a[2][4];
            #pragma unroll
            for (int mt = 0; mt < 2; mt++) {
                int rA = warpN * 32 + mt * 16 + g;
                a[mt][0] = __float_as_uint(sH[rA * HSTR + k8 + t4]);
                a[mt][1] = __float_as_uint(sH[(rA + 8) * HSTR + k8 + t4]);
                a[mt][2] = __float_as_uint(sH[rA * HSTR + k8 + t4 + 4]);
                a[mt][3] = __float_as_uint(sH[(rA + 8) * HSTR + k8 + t4 + 4]);
            }
            #pragma unroll
            for (int j = 0; j < 8; j++) {
                int cB = warpM * 64 + j * 8 + g;
                uint32_t b0 = __float_as_uint(sV[(k8 + t4) * VSTR + cB]);
                uint32_t b1 = __float_as_uint(sV[(k8 + t4 + 4) * VSTR + cB]);
                #pragma unroll
                for (int mt = 0; mt < 2; mt++)
                    mma_tf32(accO[mt][j], a[mt][0], a[mt][1], a[mt][2], a[mt][3], b0, b1);
            }
        }
    }

    // ---- Write O ----
    #pragma unroll
    for (int mt = 0; mt < 2; mt++) {
        int row = warpN * 32 + mt * 16 + g;
        #pragma unroll
        for (int j = 0; j < 8; j++) {
            int col = warpM * 64 + j * 8 + 2 * t4;
            float2 w0; w0.x = accO[mt][j][0]; w0.y = accO[mt][j][1];
            float2 w1; w1.x = accO[mt][j][2]; w1.y = accO[mt][j][3];
            *(float2*)(gO + (size_t)row * DD + col) = w0;
            *(float2*)(gO + (size_t)(row + 8) * DD + col) = w1;
        }
    }
}

extern "C" void kernel_launch(void* const* d_in, const int* in_sizes, int n_in,
                              void* d_out, int out_size) {
    const float* Q = (const float*)d_in[0];
    const float* K = (const float*)d_in[1];
    const float* U = (const float*)d_in[2];
    const float* V = (const float*)d_in[3];
    const float* R = (const float*)d_in[4];
    float* O = (float*)d_out;

    const int smem_bytes = (BN * QSTR + 2 * BM * QSTR + BM * VSTR + BN * HSTR) * 4;
    cudaFuncSetAttribute(ffnmoe_kernel, cudaFuncAttributeMaxDynamicSharedMemorySize, smem_bytes);

    dim3 grid(NN_ / BN, BH_);   // (16, 16)
    ffnmoe_kernel<<<grid, NTHREADS, smem_bytes>>>(Q, K, U, V, R, O);
}

// round 3
// speedup vs baseline: 2.1121x; 2.1121x over previous
#include <cuda_runtime.h>
#include <cuda_fp16.h>
#include <cstdint>

// Problem constants: B=2,H=8 -> BH=16, N=M=2048, D=128
#define BH_   16
#define NN_   2048
#define MM_   2048
#define DD    128

#define BN    128   // N rows per CTA
#define BM    32    // M chunk per mainloop iteration
#define NTHREADS 256

// SMEM strides in halves
#define TSTR  136   // Q/K/U/V tiles (128 cols + 8 pad): ldmatrix conflict-free
#define HSTRH 40    // Hid tile (32 cols + 8 pad)

#define SQ_OFF 0
#define SK_OFF (BN * TSTR)
#define SU_OFF (SK_OFF + BM * TSTR)
#define SV_OFF (SU_OFF + BM * TSTR)
#define SH_OFF (SV_OFF + BM * TSTR)
#define SMEM_HALVES (SH_OFF + BN * HSTRH)

__device__ __forceinline__ uint32_t saddr(const void* p) {
    return (uint32_t)__cvta_generic_to_shared(p);
}

__device__ __forceinline__ void ldsm4(uint32_t& r0, uint32_t& r1, uint32_t& r2, uint32_t& r3,
                                      uint32_t addr) {
    asm volatile("ldmatrix.sync.aligned.m8n8.x4.shared.b16 {%0,%1,%2,%3},[%4];"
                 : "=r"(r0), "=r"(r1), "=r"(r2), "=r"(r3) : "r"(addr));
}

__device__ __forceinline__ void ldsm4t(uint32_t& r0, uint32_t& r1, uint32_t& r2, uint32_t& r3,
                                       uint32_t addr) {
    asm volatile("ldmatrix.sync.aligned.m8n8.x4.trans.shared.b16 {%0,%1,%2,%3},[%4];"
                 : "=r"(r0), "=r"(r1), "=r"(r2), "=r"(r3) : "r"(addr));
}

__device__ __forceinline__ void mma_f16(float c[4], uint32_t a0, uint32_t a1, uint32_t a2,
                                        uint32_t a3, uint32_t b0, uint32_t b1) {
    asm volatile(
        "mma.sync.aligned.m16n8k16.row.col.f32.f16.f16.f32 "
        "{%0,%1,%2,%3}, {%4,%5,%6,%7}, {%8,%9}, {%0,%1,%2,%3};"
        : "+f"(c[0]), "+f"(c[1]), "+f"(c[2]), "+f"(c[3])
        : "r"(a0), "r"(a1), "r"(a2), "r"(a3), "r"(b0), "r"(b1));
}

__device__ __forceinline__ void f4_to_h2(const float4& v, uint2& w) {
    __half2 h0 = __floats2half2_rn(v.x, v.y);
    __half2 h1 = __floats2half2_rn(v.z, v.w);
    w.x = *(uint32_t*)&h0;
    w.y = *(uint32_t*)&h1;
}

__global__ __launch_bounds__(NTHREADS, 2)
void ffnmoe_kernel(const float* __restrict__ Q, const float* __restrict__ K,
                   const float* __restrict__ U, const float* __restrict__ V,
                   const float* __restrict__ R, float* __restrict__ O) {
    extern __shared__ __half sm[];
    __half* sQ = sm + SQ_OFF;
    __half* sK = sm + SK_OFF;
    __half* sU = sm + SU_OFF;
    __half* sV = sm + SV_OFF;
    __half* sH = sm + SH_OFF;

    const int bh   = blockIdx.y;
    const int n0   = blockIdx.x * BN;
    const int tid  = threadIdx.x;
    const int lane = tid & 31;
    const int warp = tid >> 5;
    const int g    = lane >> 2;        // 0..7
    const int t4   = lane & 3;         // 0..3
    const int warpN = warp >> 1;       // 0..3 -> 32-row group
    const int warpM = warp & 1;        // 0..1

    const float* gQ = Q + ((size_t)bh * NN_ + n0) * DD;
    const float* gK = K + (size_t)bh * MM_ * DD;
    const float* gU = U + (size_t)bh * MM_ * DD;
    const float* gV = V + (size_t)bh * MM_ * DD;
    const float* gR = R + ((size_t)bh * NN_ + n0) * (size_t)MM_;
    float*       gO = O + ((size_t)bh * NN_ + n0) * DD;

    // ---- Load Q tile (128x128) into SMEM as fp16 ----
    for (int f = tid; f < BN * DD / 4; f += NTHREADS) {
        int row = f >> 5;
        int c4  = (f & 31) << 2;
        float4 v = *(const float4*)(gQ + (size_t)row * DD + c4);
        uint2 w; f4_to_h2(v, w);
        *(uint2*)(sQ + row * TSTR + c4) = w;
    }

    // O accumulators: warp tile 32 rows x 64 cols = 2 mtiles x 8 ntiles
    float accO[2][8][4];
    #pragma unroll
    for (int i = 0; i < 2; i++)
        #pragma unroll
        for (int j = 0; j < 8; j++)
            #pragma unroll
            for (int k = 0; k < 4; k++) accO[i][j][k] = 0.f;

    // precomputed fragment address components
    const int lr16 = lane & 15;            // row within 16
    const int lc8  = (lane >> 4) << 3;     // 0 or 8
    const int vr   = lane & 7;             // trans ldsm row
    const int vko  = ((lane >> 3) & 1) << 3;
    const int vno  = (lane >> 4) << 3;

    for (int m0 = 0; m0 < MM_; m0 += BM) {
        // ---- Prefetch R for this chunk into registers (hides under GEMM1) ----
        float2 rr[2][2][2];
        #pragma unroll
        for (int mt = 0; mt < 2; mt++)
            #pragma unroll
            for (int nt = 0; nt < 2; nt++) {
                int row = warpN * 32 + mt * 16 + g;
                int col = m0 + warpM * 16 + nt * 8 + 2 * t4;
                rr[mt][nt][0] = *(const float2*)(gR + (size_t)row * MM_ + col);
                rr[mt][nt][1] = *(const float2*)(gR + (size_t)(row + 8) * MM_ + col);
            }

        __syncthreads();   // previous iteration done reading sK/sU/sV/sH

        // ---- Load K, U, V chunks (32x128 each) as fp16 ----
        for (int f = tid; f < BM * DD / 4; f += NTHREADS) {
            int row = f >> 5;
            int c4  = (f & 31) << 2;
            size_t goff = (size_t)(m0 + row) * DD + c4;
            float4 kv = *(const float4*)(gK + goff);
            float4 uv = *(const float4*)(gU + goff);
            float4 vv = *(const float4*)(gV + goff);
            uint2 w;
            f4_to_h2(kv, w); *(uint2*)(sK + row * TSTR + c4) = w;
            f4_to_h2(uv, w); *(uint2*)(sU + row * TSTR + c4) = w;
            f4_to_h2(vv, w); *(uint2*)(sV + row * TSTR + c4) = w;
        }
        __syncthreads();

        // ---- GEMM1: S = Q*K^T, T = Q*U^T  (warp: 32x16 of the 128x32 S/T) ----
        float accS[2][2][4] = {};
        float accT[2][2][4] = {};
        #pragma unroll
        for (int kk = 0; kk < DD / 16; kk++) {
            const int k16 = kk * 16;
            uint32_t a[2][4];
            #pragma unroll
            for (int mt = 0; mt < 2; mt++) {
                uint32_t ad = saddr(sQ + (warpN * 32 + mt * 16 + lr16) * TSTR + k16 + lc8);
                ldsm4(a[mt][0], a[mt][1], a[mt][2], a[mt][3], ad);
            }
            uint32_t bk[4], bu[4];
            {
                int boff = (warpM * 16 + lr16) * TSTR + k16 + lc8;
                ldsm4(bk[0], bk[1], bk[2], bk[3], saddr(sK + boff));
                ldsm4(bu[0], bu[1], bu[2], bu[3], saddr(sU + boff));
            }
            #pragma unroll
            for (int nt = 0; nt < 2; nt++) {
                #pragma unroll
                for (int mt = 0; mt < 2; mt++) {
                    mma_f16(accS[mt][nt], a[mt][0], a[mt][1], a[mt][2], a[mt][3],
                            bk[nt], bk[nt + 2]);
                    mma_f16(accT[mt][nt], a[mt][0], a[mt][1], a[mt][2], a[mt][3],
                            bu[nt], bu[nt + 2]);
                }
            }
        }

        // ---- Elementwise: Hid = relu(S)*T*R -> sH (fp16) ----
        #pragma unroll
        for (int mt = 0; mt < 2; mt++) {
            #pragma unroll
            for (int nt = 0; nt < 2; nt++) {
                int row  = warpN * 32 + mt * 16 + g;
                int colL = warpM * 16 + nt * 8 + 2 * t4;
                float2 r0 = rr[mt][nt][0];
                float2 r1 = rr[mt][nt][1];
                float h0 = fmaxf(accS[mt][nt][0], 0.f) * accT[mt][nt][0] * r0.x;
                float h1 = fmaxf(accS[mt][nt][1], 0.f) * accT[mt][nt][1] * r0.y;
                float h2 = fmaxf(accS[mt][nt][2], 0.f) * accT[mt][nt][2] * r1.x;
                float h3 = fmaxf(accS[mt][nt][3], 0.f) * accT[mt][nt][3] * r1.y;
                __half2 w0 = __floats2half2_rn(h0, h1);
                __half2 w1 = __floats2half2_rn(h2, h3);
                *(__half2*)(sH + row * HSTRH + colL) = w0;
                *(__half2*)(sH + (row + 8) * HSTRH + colL) = w1;
            }
        }
        __syncthreads();

        // ---- GEMM2: O += Hid * V  (warp: 32 x 64 of the 128x128 O) ----
        #pragma unroll
        for (int kk = 0; kk < BM / 16; kk++) {
            const int k16 = kk * 16;
            uint32_t a[2][4];
            #pragma unroll
            for (int mt = 0; mt < 2; mt++) {
                uint32_t ad = saddr(sH + (warpN * 32 + mt * 16 + lr16) * HSTRH + k16 + lc8);
                ldsm4(a[mt][0], a[mt][1], a[mt][2], a[mt][3], ad);
            }
            uint32_t bb[4][4];
            #pragma unroll
            for (int q = 0; q < 4; q++) {
                int nb = warpM * 64 + q * 16;
                uint32_t ad = saddr(sV + (k16 + vr + vko) * TSTR + nb + vno);
                ldsm4t(bb[q][0], bb[q][1], bb[q][2], bb[q][3], ad);
            }
            #pragma unroll
            for (int q = 0; q < 4; q++) {
                #pragma unroll
                for (int jj = 0; jj < 2; jj++) {
                    int j = q * 2 + jj;
                    uint32_t b0 = bb[q][jj * 2];
                    uint32_t b1 = bb[q][jj * 2 + 1];
                    #pragma unroll
                    for (int mt = 0; mt < 2; mt++)
                        mma_f16(accO[mt][j], a[mt][0], a[mt][1], a[mt][2], a[mt][3], b0, b1);
                }
            }
        }
    }

    // ---- Write O ----
    #pragma unroll
    for (int mt = 0; mt < 2; mt++) {
        int row = warpN * 32 + mt * 16 + g;
        #pragma unroll
        for (int j = 0; j < 8; j++) {
            int col = warpM * 64 + j * 8 + 2 * t4;
            float2 w0; w0.x = accO[mt][j][0]; w0.y = accO[mt][j][1];
            float2 w1; w1.x = accO[mt][j][2]; w1.y = accO[mt][j][3];
            *(float2*)(gO + (size_t)row * DD + col) = w0;
            *(float2*)(gO + (size_t)(row + 8) * DD + col) = w1;
        }
    }
}

extern "C" void kernel_launch(void* const* d_in, const int* in_sizes, int n_in,
                              void* d_out, int out_size) {
    const float* Q = (const float*)d_in[0];
    const float* K = (const float*)d_in[1];
    const float* U = (const float*)d_in[2];
    const float* V = (const float*)d_in[3];
    const float* R = (const float*)d_in[4];
    float* O = (float*)d_out;

    const int smem_bytes = SMEM_HALVES * (int)sizeof(__half);
    cudaFuncSetAttribute(ffnmoe_kernel, cudaFuncAttributeMaxDynamicSharedMemorySize, smem_bytes);

    dim3 grid(NN_ / BN, BH_);   // (16, 16)
    ffnmoe_kernel<<<grid, NTHREADS, smem_bytes>>>(Q, K, U, V, R, O);
}

// round 4
// speedup vs baseline: 2.8185x; 1.3345x over previous
#include <cuda_runtime.h>
#include <cuda_fp16.h>
#include <cstdint>

// Problem constants: B=2,H=8 -> BH=16, N=M=2048, D=128
#define BH_   16
#define NN_   2048
#define MM_   2048
#define DD    128

#define BN    128            // N rows per CTA
#define BM    32             // M chunk per iteration
#define NTHREADS 256
#define NIT   (MM_ / BM)     // 64

#define TSTR  136            // padded row stride (halves): conflict-free ldmatrix
#define STAGE_HALVES (3 * BM * TSTR)          // K,U,V one stage
#define SKUV_OFF     (BN * TSTR)              // after Q tile
#define SMEM_HALVES  (SKUV_OFF + 2 * STAGE_HALVES)

#define TELEMS (BH_ * MM_ * DD)               // 4,194,304 per tensor

// fp16 copies of Q,K,U,V (written by convert kernel, read by main kernel)
__device__ __half g_h[4][TELEMS];

__device__ __forceinline__ uint32_t saddr(const void* p) {
    return (uint32_t)__cvta_generic_to_shared(p);
}

__device__ __forceinline__ void cpa16(uint32_t d, const void* s) {
    asm volatile("cp.async.cg.shared.global [%0], [%1], 16;" :: "r"(d), "l"(s));
}

__device__ __forceinline__ void ldsm4(uint32_t& r0, uint32_t& r1, uint32_t& r2, uint32_t& r3,
                                      uint32_t addr) {
    asm volatile("ldmatrix.sync.aligned.m8n8.x4.shared.b16 {%0,%1,%2,%3},[%4];"
                 : "=r"(r0), "=r"(r1), "=r"(r2), "=r"(r3) : "r"(addr));
}

__device__ __forceinline__ void ldsm4t(uint32_t& r0, uint32_t& r1, uint32_t& r2, uint32_t& r3,
                                       uint32_t addr) {
    asm volatile("ldmatrix.sync.aligned.m8n8.x4.trans.shared.b16 {%0,%1,%2,%3},[%4];"
                 : "=r"(r0), "=r"(r1), "=r"(r2), "=r"(r3) : "r"(addr));
}

__device__ __forceinline__ void mma_f16(float c[4], uint32_t a0, uint32_t a1, uint32_t a2,
                                        uint32_t a3, uint32_t b0, uint32_t b1) {
    asm volatile(
        "mma.sync.aligned.m16n8k16.row.col.f32.f16.f16.f32 "
        "{%0,%1,%2,%3}, {%4,%5,%6,%7}, {%8,%9}, {%0,%1,%2,%3};"
        : "+f"(c[0]), "+f"(c[1]), "+f"(c[2]), "+f"(c[3])
        : "r"(a0), "r"(a1), "r"(a2), "r"(a3), "r"(b0), "r"(b1));
}

// ---------------- Kernel 1: f32 -> f16 conversion of Q,K,U,V ----------------
__global__ __launch_bounds__(256)
void convert_kernel(const float* __restrict__ q, const float* __restrict__ k,
                    const float* __restrict__ u, const float* __restrict__ v) {
    const int t = blockIdx.y;
    const float* src = (t == 0) ? q : (t == 1) ? k : (t == 2) ? u : v;
    const int i = blockIdx.x * 256 + threadIdx.x;          // < TELEMS/4
    float4 x = ((const float4*)src)[i];
    __half2 h0 = __floats2half2_rn(x.x, x.y);
    __half2 h1 = __floats2half2_rn(x.z, x.w);
    uint2 w;
    w.x = *(uint32_t*)&h0;
    w.y = *(uint32_t*)&h1;
    ((uint2*)g_h[t])[i] = w;
}

// ---------------- helper: issue cp.async for one K/U/V stage ----------------
__device__ __forceinline__ void issue_stage(__half* base, const __half* gK, const __half* gU,
                                            const __half* gV, int m0, int tid) {
    #pragma unroll
    for (int ii = 0; ii < 2; ii++) {                        // 512 ops / 256 threads
        int i   = tid + ii * NTHREADS;
        int row = i >> 4;
        int c8  = (i & 15) << 3;
        size_t go = (size_t)(m0 + row) * DD + c8;
        uint32_t so = (uint32_t)(row * TSTR + c8);
        cpa16(saddr(base + so), gK + go);
        cpa16(saddr(base + BM * TSTR + so), gU + go);
        cpa16(saddr(base + 2 * BM * TSTR + so), gV + go);
    }
}

// ---------------- Kernel 2: fused pipelined FFN-MoE ----------------
__global__ __launch_bounds__(NTHREADS, 2)
void ffnmoe_main(const float* __restrict__ R, float* __restrict__ O) {
    extern __shared__ __half sm[];
    __half* sQ = sm;

    const int bh   = blockIdx.y;
    const int n0   = blockIdx.x * BN;
    const int tid  = threadIdx.x;
    const int lane = tid & 31;
    const int warp = tid >> 5;
    const int g    = lane >> 2;               // 0..7
    const int t4   = lane & 3;                // 0..3
    const int lr16 = lane & 15;
    const int lc8  = (lane >> 4) << 3;
    const int vr   = (lane & 7) + (((lane >> 3) & 1) << 3);   // 0..15
    const int vno  = (lane >> 4) << 3;

    const __half* gQh = g_h[0] + ((size_t)bh * NN_ + n0) * DD;
    const __half* gKh = g_h[1] + (size_t)bh * MM_ * DD;
    const __half* gUh = g_h[2] + (size_t)bh * MM_ * DD;
    const __half* gVh = g_h[3] + (size_t)bh * MM_ * DD;
    const float*  gR  = R + ((size_t)bh * NN_ + n0) * (size_t)MM_;
    float*        gO  = O + ((size_t)bh * NN_ + n0) * DD;

    // ---- Prologue: Q tile + stage 0 via cp.async, one group ----
    #pragma unroll
    for (int ii = 0; ii < 8; ii++) {                       // 2048 ops / 256 threads
        int i   = tid + ii * NTHREADS;
        int row = i >> 4;
        int c8  = (i & 15) << 3;
        cpa16(saddr(sQ + row * TSTR + c8), gQh + (size_t)row * DD + c8);
    }
    issue_stage(sm + SKUV_OFF, gKh, gUh, gVh, 0, tid);
    asm volatile("cp.async.commit_group;" ::: "memory");

    float accO[16][4];
    #pragma unroll
    for (int j = 0; j < 16; j++)
        #pragma unroll
        for (int c = 0; c < 4; c++) accO[j][c] = 0.f;

    const int qrow = warp * 16 + lr16;

    for (int it = 0; it < NIT; it++) {
        const int m0 = it * BM;
        __half* cur = sm + SKUV_OFF + (it & 1) * STAGE_HALVES;
        __half* sK = cur;
        __half* sU = cur + BM * TSTR;
        __half* sV = cur + 2 * BM * TSTR;

        // ---- R prefetch (latency hidden under GEMM1) ----
        float2 rr[4][2];
        #pragma unroll
        for (int nt = 0; nt < 4; nt++) {
            const float* rp = gR + (size_t)(warp * 16 + g) * MM_ + m0 + nt * 8 + 2 * t4;
            rr[nt][0] = *(const float2*)rp;
            rr[nt][1] = *(const float2*)(rp + (size_t)8 * MM_);
        }

        asm volatile("cp.async.wait_group 0;" ::: "memory");
        __syncthreads();   // stage `it` visible to all; all warps past previous chunk

        // ---- Issue next stage (flies under this chunk's compute) ----
        if (it + 1 < NIT) {
            __half* nb = sm + SKUV_OFF + ((it + 1) & 1) * STAGE_HALVES;
            issue_stage(nb, gKh, gUh, gVh, m0 + BM, tid);
        }
        asm volatile("cp.async.commit_group;" ::: "memory");

        // ---- GEMM1 (two passes of n16) + gate -> packed A fragments ----
        uint32_t pk[2][4];
        #pragma unroll
        for (int p = 0; p < 2; p++) {
            float accS[2][4] = {};
            float accT[2][4] = {};
            #pragma unroll
            for (int kk = 0; kk < 8; kk++) {
                const int k16 = kk * 16;
                uint32_t a0, a1, a2, a3;
                ldsm4(a0, a1, a2, a3, saddr(sQ + qrow * TSTR + k16 + lc8));
                uint32_t bk0, bk1, bk2, bk3;
                ldsm4(bk0, bk1, bk2, bk3, saddr(sK + (p * 16 + lr16) * TSTR + k16 + lc8));
                uint32_t bu0, bu1, bu2, bu3;
                ldsm4(bu0, bu1, bu2, bu3, saddr(sU + (p * 16 + lr16) * TSTR + k16 + lc8));
                mma_f16(accS[0], a0, a1, a2, a3, bk0, bk2);
                mma_f16(accS[1], a0, a1, a2, a3, bk1, bk3);
                mma_f16(accT[0], a0, a1, a2, a3, bu0, bu2);
                mma_f16(accT[1], a0, a1, a2, a3, bu1, bu3);
            }
            #pragma unroll
            for (int j = 0; j < 2; j++) {
                const int nt = 2 * p + j;
                float2 r0 = rr[nt][0];
                float2 r1 = rr[nt][1];
                float h0 = fmaxf(accS[j][0], 0.f) * accT[j][0] * r0.x;
                float h1 = fmaxf(accS[j][1], 0.f) * accT[j][1] * r0.y;
                float h2 = fmaxf(accS[j][2], 0.f) * accT[j][2] * r1.x;
                float h3 = fmaxf(accS[j][3], 0.f) * accT[j][3] * r1.y;
                __half2 p01 = __floats2half2_rn(h0, h1);
                __half2 p23 = __floats2half2_rn(h2, h3);
                pk[p][j ? 2 : 0] = *(uint32_t*)&p01;
                pk[p][j ? 3 : 1] = *(uint32_t*)&p23;
            }
        }

        // ---- GEMM2: O += Hid(reg) * V(smem) ----
        #pragma unroll
        for (int s = 0; s < 2; s++) {
            #pragma unroll
            for (int q = 0; q < 8; q++) {
                uint32_t b0, b1, b2, b3;
                ldsm4t(b0, b1, b2, b3, saddr(sV + (s * 16 + vr) * TSTR + q * 16 + vno));
                mma_f16(accO[2 * q],     pk[s][0], pk[s][1], pk[s][2], pk[s][3], b0, b1);
                mma_f16(accO[2 * q + 1], pk[s][0], pk[s][1], pk[s][2], pk[s][3], b2, b3);
            }
        }
    }

    // ---- Write O ----
    #pragma unroll
    for (int j = 0; j < 16; j++) {
        const int col = j * 8 + 2 * t4;
        float2 w0; w0.x = accO[j][0]; w0.y = accO[j][1];
        float2 w1; w1.x = accO[j][2]; w1.y = accO[j][3];
        *(float2*)(gO + (size_t)(warp * 16 + g) * DD + col) = w0;
        *(float2*)(gO + (size_t)(warp * 16 + g + 8) * DD + col) = w1;
    }
}

extern "C" void kernel_launch(void* const* d_in, const int* in_sizes, int n_in,
                              void* d_out, int out_size) {
    const float* Q = (const float*)d_in[0];
    const float* K = (const float*)d_in[1];
    const float* U = (const float*)d_in[2];
    const float* V = (const float*)d_in[3];
    const float* R = (const float*)d_in[4];
    float* O = (float*)d_out;

    // Kernel 1: convert Q,K,U,V to fp16 scratch
    dim3 cgrid(TELEMS / 4 / 256, 4);
    convert_kernel<<<cgrid, 256>>>(Q, K, U, V);

    // Kernel 2: fused main
    const int smem_bytes = SMEM_HALVES * (int)sizeof(__half);   // 87,040 B
    cudaFuncSetAttribute(ffnmoe_main, cudaFuncAttributeMaxDynamicSharedMemorySize, smem_bytes);
    dim3 grid(NN_ / BN, BH_);   // (16, 16)
    ffnmoe_main<<<grid, NTHREADS, smem_bytes>>>(R, O);
}

// round 13
// speedup vs baseline: 3.3079x; 1.1736x over previous
#include <cuda_runtime.h>
#include <cuda_fp16.h>
#include <cstdint>

// Problem constants: B=2,H=8 -> BH=16, N=M=2048, D=128
#define BH_   16
#define NN_   2048
#define MM_   2048
#define DD    128

#define BN    128            // N rows per CTA
#define BM    32             // M chunk per iteration
#define NTHREADS 256
#define NIT   (MM_ / BM)     // 64

// SMEM strides
#define TSTR  136            // Q/K/U/V row stride (halves): conflict-free ldmatrix
#define HSTR  40             // Hid row stride (halves)
#define RSTR  36             // R row stride (f32)

// SMEM layout (halves)
#define SQ_OFF   0
#define STG_H    (3 * BM * TSTR)                  // 13056 halves per K/U/V stage
#define SKUV_OFF (BN * TSTR)                      // 17408
#define SR_OFF   (SKUV_OFF + 2 * STG_H)           // 43520 (R: 128*36 f32 = 9216 halves)
#define SH_OFF   (SR_OFF + BN * RSTR * 2)         // 52736
#define SMEM_HALVES (SH_OFF + BN * HSTR)          // 57856 -> 115712 B

#define TELEMS (BH_ * MM_ * DD)

// fp16 copies of Q,K,U,V
__device__ __half g_h[4][TELEMS];

__device__ __forceinline__ uint32_t saddr(const void* p) {
    return (uint32_t)__cvta_generic_to_shared(p);
}
__device__ __forceinline__ void cpa16(uint32_t d, const void* s) {
    asm volatile("cp.async.cg.shared.global [%0], [%1], 16;" :: "r"(d), "l"(s));
}
__device__ __forceinline__ void ldsm4(uint32_t& r0, uint32_t& r1, uint32_t& r2, uint32_t& r3,
                                      uint32_t addr) {
    asm volatile("ldmatrix.sync.aligned.m8n8.x4.shared.b16 {%0,%1,%2,%3},[%4];"
                 : "=r"(r0), "=r"(r1), "=r"(r2), "=r"(r3) : "r"(addr));
}
__device__ __forceinline__ void ldsm4t(uint32_t& r0, uint32_t& r1, uint32_t& r2, uint32_t& r3,
                                       uint32_t addr) {
    asm volatile("ldmatrix.sync.aligned.m8n8.x4.trans.shared.b16 {%0,%1,%2,%3},[%4];"
                 : "=r"(r0), "=r"(r1), "=r"(r2), "=r"(r3) : "r"(addr));
}
__device__ __forceinline__ void mma_f16(float c[4], uint32_t a0, uint32_t a1, uint32_t a2,
                                        uint32_t a3, uint32_t b0, uint32_t b1) {
    asm volatile(
        "mma.sync.aligned.m16n8k16.row.col.f32.f16.f16.f32 "
        "{%0,%1,%2,%3}, {%4,%5,%6,%7}, {%8,%9}, {%0,%1,%2,%3};"
        : "+f"(c[0]), "+f"(c[1]), "+f"(c[2]), "+f"(c[3])
        : "r"(a0), "r"(a1), "r"(a2), "r"(a3), "r"(b0), "r"(b1));
}
__device__ __forceinline__ void f4_to_h2(const float4& v, uint2& w) {
    __half2 h0 = __floats2half2_rn(v.x, v.y);
    __half2 h1 = __floats2half2_rn(v.z, v.w);
    w.x = *(uint32_t*)&h0;
    w.y = *(uint32_t*)&h1;
}
#define CP_COMMIT() asm volatile("cp.async.commit_group;" ::: "memory")
#define CP_WAIT0()  asm volatile("cp.async.wait_group 0;" ::: "memory")

// ---------------- Kernel 1: f32 -> f16 conversion of Q,K,U,V ----------------
__global__ __launch_bounds__(256)
void convert_kernel(const float* __restrict__ q, const float* __restrict__ k,
                    const float* __restrict__ u, const float* __restrict__ v) {
    const int t = blockIdx.y;
    const float* src = (t == 0) ? q : (t == 1) ? k : (t == 2) ? u : v;
    const int i = blockIdx.x * 256 + threadIdx.x;
    float4 x = ((const float4*)src)[i];
    uint2 w; f4_to_h2(x, w);
    ((uint2*)g_h[t])[i] = w;
}

// ---------------- stage loaders ----------------
__device__ __forceinline__ void issue_kuv(__half* base, const __half* gK, const __half* gU,
                                          const __half* gV, int m0, int tid) {
    #pragma unroll
    for (int ii = 0; ii < 2; ii++) {                 // 512 slots / 256 threads
        int i   = tid + ii * NTHREADS;
        int row = i >> 4;
        int c8  = (i & 15) << 3;
        size_t go = (size_t)(m0 + row) * DD + c8;
        uint32_t so = (uint32_t)(row * TSTR + c8);
        cpa16(saddr(base + so), gK + go);
        cpa16(saddr(base + BM * TSTR + so), gU + go);
        cpa16(saddr(base + 2 * BM * TSTR + so), gV + go);
    }
}
__device__ __forceinline__ void issue_r(float* sR, const float* gR, int m0, int tid) {
    #pragma unroll
    for (int ii = 0; ii < 4; ii++) {                 // 1024 slots / 256 threads
        int i   = tid + ii * NTHREADS;
        int row = i >> 3;
        int c4  = (i & 7) << 2;
        cpa16(saddr(sR + row * RSTR + c4), gR + (size_t)row * MM_ + m0 + c4);
    }
}

// ---------------- Kernel 2: fused pipelined FFN-MoE ----------------
__global__ __launch_bounds__(NTHREADS, 2)
void ffnmoe_main(const float* __restrict__ R, float* __restrict__ O) {
    extern __shared__ __half sm[];
    __half* sQ = sm + SQ_OFF;
    float*  sR = (float*)(sm + SR_OFF);
    __half* sH = sm + SH_OFF;

    const int bh   = blockIdx.y;
    const int n0   = blockIdx.x * BN;
    const int tid  = threadIdx.x;
    const int lane = tid & 31;
    const int warp = tid >> 5;
    const int g    = lane >> 2;               // 0..7
    const int t4   = lane & 3;                // 0..3
    const int lr16 = lane & 15;
    const int lc8  = (lane >> 4) << 3;
    const int vr   = (lane & 7) + (((lane >> 3) & 1) << 3);   // 0..15
    const int vno  = (lane >> 4) << 3;
    const int warpN = warp >> 1;              // 0..3 -> 32-row group
    const int warpM = warp & 1;               // 0..1 -> col split

    const __half* gQh = g_h[0] + ((size_t)bh * NN_ + n0) * DD;
    const __half* gKh = g_h[1] + (size_t)bh * MM_ * DD;
    const __half* gUh = g_h[2] + (size_t)bh * MM_ * DD;
    const __half* gVh = g_h[3] + (size_t)bh * MM_ * DD;
    const float*  gR  = R + ((size_t)bh * NN_ + n0) * (size_t)MM_;
    float*        gO  = O + ((size_t)bh * NN_ + n0) * DD;

    // ---- Prologue: Q tile + stage 0 (K/U/V + R) ----
    #pragma unroll
    for (int ii = 0; ii < 8; ii++) {
        int i   = tid + ii * NTHREADS;
        int row = i >> 4;
        int c8  = (i & 15) << 3;
        cpa16(saddr(sQ + row * TSTR + c8), gQh + (size_t)row * DD + c8);
    }
    issue_kuv(sm + SKUV_OFF, gKh, gUh, gVh, 0, tid);
    issue_r(sR, gR, 0, tid);
    CP_COMMIT();

    float accO[2][8][4];
    #pragma unroll
    for (int mt = 0; mt < 2; mt++)
        #pragma unroll
        for (int j = 0; j < 8; j++)
            #pragma unroll
            for (int c = 0; c < 4; c++) accO[mt][j][c] = 0.f;

    for (int it = 0; it < NIT; it++) {
        const int m0 = it * BM;
        __half* cur = sm + SKUV_OFF + (it & 1) * STG_H;
        __half* sK = cur;
        __half* sU = cur + BM * TSTR;
        __half* sV = cur + 2 * BM * TSTR;

        CP_WAIT0();
        __syncthreads();          // stage it (K/U/V + R) visible; prev iter done

        // ---- Issue K/U/V for it+1 into the other buffer ----
        if (it + 1 < NIT) {
            issue_kuv(sm + SKUV_OFF + ((it + 1) & 1) * STG_H, gKh, gUh, gVh, m0 + BM, tid);
        }
        CP_COMMIT();

        // ---- GEMM1: warp computes S,T for 32 rows x 16 cols ----
        float accS[2][2][4] = {};
        float accT[2][2][4] = {};
        #pragma unroll
        for (int kk = 0; kk < 8; kk++) {
            const int k16 = kk * 16;
            uint32_t a[2][4];
            #pragma unroll
            for (int mt = 0; mt < 2; mt++)
                ldsm4(a[mt][0], a[mt][1], a[mt][2], a[mt][3],
                      saddr(sQ + (warpN * 32 + mt * 16 + lr16) * TSTR + k16 + lc8));
            uint32_t bk[4], bu[4];
            {
                int boff = (warpM * 16 + lr16) * TSTR + k16 + lc8;
                ldsm4(bk[0], bk[1], bk[2], bk[3], saddr(sK + boff));
                ldsm4(bu[0], bu[1], bu[2], bu[3], saddr(sU + boff));
            }
            #pragma unroll
            for (int nt = 0; nt < 2; nt++)
                #pragma unroll
                for (int mt = 0; mt < 2; mt++) {
                    mma_f16(accS[mt][nt], a[mt][0], a[mt][1], a[mt][2], a[mt][3],
                            bk[nt], bk[nt + 2]);
                    mma_f16(accT[mt][nt], a[mt][0], a[mt][1], a[mt][2], a[mt][3],
                            bu[nt], bu[nt + 2]);
                }
        }

        // ---- Gate: Hid = relu(S)*T*R -> sH (fp16), R read from SMEM ----
        #pragma unroll
        for (int mt = 0; mt < 2; mt++)
            #pragma unroll
            for (int nt = 0; nt < 2; nt++) {
                int row  = warpN * 32 + mt * 16 + g;
                int colL = warpM * 16 + nt * 8 + 2 * t4;
                float2 r0 = *(float2*)&sR[row * RSTR + colL];
                float2 r1 = *(float2*)&sR[(row + 8) * RSTR + colL];
                float h0 = fmaxf(accS[mt][nt][0], 0.f) * accT[mt][nt][0] * r0.x;
                float h1 = fmaxf(accS[mt][nt][1], 0.f) * accT[mt][nt][1] * r0.y;
                float h2 = fmaxf(accS[mt][nt][2], 0.f) * accT[mt][nt][2] * r1.x;
                float h3 = fmaxf(accS[mt][nt][3], 0.f) * accT[mt][nt][3] * r1.y;
                __half2 w0 = __floats2half2_rn(h0, h1);
                __half2 w1 = __floats2half2_rn(h2, h3);
                *(__half2*)(sH + row * HSTR + colL) = w0;
                *(__half2*)(sH + (row + 8) * HSTR + colL) = w1;
            }
        __syncthreads();          // Hid complete; all R reads of stage it done

        // ---- Issue R for it+1 (single buffer, safe after the sync above) ----
        if (it + 1 < NIT) {
            issue_r(sR, gR, m0 + BM, tid);
        }
        CP_COMMIT();

        // ---- GEMM2: O += Hid * V  (warp: 32 rows x 64 cols) ----
        #pragma unroll
        for (int kk = 0; kk < 2; kk++) {
            const int k16 = kk * 16;
            uint32_t a2[2][4];
            #pragma unroll
            for (int mt = 0; mt < 2; mt++)
                ldsm4(a2[mt][0], a2[mt][1], a2[mt][2], a2[mt][3],
                      saddr(sH + (warpN * 32 + mt * 16 + lr16) * HSTR + k16 + lc8));
            #pragma unroll
            for (int q = 0; q < 4; q++) {
                uint32_t b0, b1, b2, b3;
                ldsm4t(b0, b1, b2, b3,
                       saddr(sV + (k16 + vr) * TSTR + warpM * 64 + q * 16 + vno));
                #pragma unroll
                for (int mt = 0; mt < 2; mt++) {
                    mma_f16(accO[mt][2 * q],     a2[mt][0], a2[mt][1], a2[mt][2], a2[mt][3], b0, b1);
                    mma_f16(accO[mt][2 * q + 1], a2[mt][0], a2[mt][1], a2[mt][2], a2[mt][3], b2, b3);
                }
            }
        }
    }

    // ---- Write O ----
    #pragma unroll
    for (int mt = 0; mt < 2; mt++) {
        int row = warpN * 32 + mt * 16 + g;
        #pragma unroll
        for (int j = 0; j < 8; j++) {
            int col = warpM * 64 + j * 8 + 2 * t4;
            float2 w0; w0.x = accO[mt][j][0]; w0.y = accO[mt][j][1];
            float2 w1; w1.x = accO[mt][j][2]; w1.y = accO[mt][j][3];
            *(float2*)(gO + (size_t)row * DD + col) = w0;
            *(float2*)(gO + (size_t)(row + 8) * DD + col) = w1;
        }
    }
}

extern "C" void kernel_launch(void* const* d_in, const int* in_sizes, int n_in,
                              void* d_out, int out_size) {
    const float* Q = (const float*)d_in[0];
    const float* K = (const float*)d_in[1];
    const float* U = (const float*)d_in[2];
    const float* V = (const float*)d_in[3];
    const float* R = (const float*)d_in[4];
    float* O = (float*)d_out;

    dim3 cgrid(TELEMS / 4 / 256, 4);
    convert_kernel<<<cgrid, 256>>>(Q, K, U, V);

    const int smem_bytes = SMEM_HALVES * (int)sizeof(__half);   // 115,712 B
    cudaFuncSetAttribute(ffnmoe_main, cudaFuncAttributeMaxDynamicSharedMemorySize, smem_bytes);
    dim3 grid(NN_ / BN, BH_);   // (16, 16)
    ffnmoe_main<<<grid, NTHREADS, smem_bytes>>>(R, O);
}